// round 7
// baseline (speedup 1.0000x reference)
#include <cuda_runtime.h>
#include <cuda_bf16.h>
#include <cstdint>

// Problem constants
#define BB 4
#define VV 4
#define NN 1000
#define IN_F 64
#define HEADS 4
#define OUT_F 32
#define DD 128           // HEADS*OUT_F
#define EE 64000
#define NTOT 4000        // B*N
#define ETOT 68000       // E + self loops
#define ROWS 16000       // B*V*N
#define NEG_SLOPE 0.2f

// ---------------- scratch (static device globals; no allocation) -------------
__device__ float g_h[ROWS * DD];        // GAT linear output, row=(b*4+v)*1000+n
__device__ float g_hgat[ROWS * DD];     // GAT aggregated output
__device__ float g_qkv[ROWS * 384];     // in_proj output
__device__ float g_ao[ROWS * DD];       // attention output
__device__ float g_ssrc[NTOT * HEADS];  // zero-init; only i<NN ever written
__device__ float g_sdst[NTOT * HEADS];  // zero-init; only i<NN ever written
__device__ int   g_deg[NTOT];           // zero at load; scan resets to zero each run
__device__ int   g_off[NTOT + 1];
__device__ int   g_cur[NTOT];
__device__ int   g_csr[ETOT];
__device__ int   g_is64;                // 1 if edge_index is int64, 0 if int32

// ---------------- edge dtype detection --------------------------------------
// If edge_index is int64 (values in [0,4000)), every odd 32-bit word is the
// zero high half. If int32, odd words are real ids ~U[0,4000):
// P(512 zeros) == 0 in practice. Deterministic given the input.
__global__ void detect_dtype(const unsigned int* __restrict__ w) {
    unsigned int any = 0;
    for (int i = threadIdx.x; i < 512; i += 32)
        any |= w[2 * i + 1];
    #pragma unroll
    for (int o = 16; o; o >>= 1)
        any |= __shfl_xor_sync(0xffffffffu, any, o);
    if (threadIdx.x == 0) g_is64 = (any == 0u) ? 1 : 0;
}

__device__ __forceinline__ int edge_at(const void* ei, int idx) {
    if (g_is64) return (int)((const long long*)ei)[idx];
    return ((const int*)ei)[idx];
}

// ---------------- tiled fp32 GEMM: C[M][Nn] = A[M][K] @ B[Nn][K]^T -----------
// 128x128 tile, 256 threads, 8x8 microtile, K-step 16, K a template constant
// (fully unrolled mainloop, front-batched prefetch LDGs, no live guard preds).
// Double-buffered smem: one barrier per mainloop iteration.
// SCORES: fused GATv2 per-node score epilogue (valid only when grid.x==1 so a
// CTA owns full 128-wide rows; writes g_ssrc/g_sdst for rows < NN).
// Requires: M % 128 == 0, Nn % 128 == 0, K % 16 == 0 (true for all call sites).
template <int K, bool SCORES>
__global__ __launch_bounds__(256) void gemm_tn(
    const float* __restrict__ A, const float* __restrict__ Bm,
    const float* __restrict__ bias1, const float* __restrict__ bias2,
    const float* __restrict__ att,
    float* __restrict__ C, int Nn)
{
    __shared__ float As[2][16][132];   // [buf][k][m], padded (132 % 32 == 4)
    __shared__ float Bs[2][16][132];   // [buf][k][n]
    const int tid = threadIdx.x;
    const int tx = tid & 15;        // 0..15 -> col group (8 cols)
    const int ty = tid >> 4;        // 0..15 -> row group (8 rows)
    const int rowBase = blockIdx.y * 128;
    const int colBase = blockIdx.x * 128;

    // per-thread load coordinates: two A rows, two B rows, same k-quad
    const int ra0 = tid >> 2;            // 0..63
    const int ra1 = ra0 + 64;            // 64..127
    const int ca0 = (tid & 3) << 2;      // 0,4,8,12

    float acc[8][8] = {};
    float ar[8], br[8];
    float4 aP0, aP1, bP0, bP1;

    const float* Arow0 = A  + (size_t)(rowBase + ra0) * K + ca0;
    const float* Arow1 = A  + (size_t)(rowBase + ra1) * K + ca0;
    const float* Brow0 = Bm + (size_t)(colBase + ra0) * K + ca0;
    const float* Brow1 = Bm + (size_t)(colBase + ra1) * K + ca0;

    // prologue: prefetch tile k0=0 and commit to buffer 0
    aP0 = *(const float4*)(Arow0);
    aP1 = *(const float4*)(Arow1);
    bP0 = *(const float4*)(Brow0);
    bP1 = *(const float4*)(Brow1);
    As[0][ca0 + 0][ra0] = aP0.x; As[0][ca0 + 1][ra0] = aP0.y;
    As[0][ca0 + 2][ra0] = aP0.z; As[0][ca0 + 3][ra0] = aP0.w;
    As[0][ca0 + 0][ra1] = aP1.x; As[0][ca0 + 1][ra1] = aP1.y;
    As[0][ca0 + 2][ra1] = aP1.z; As[0][ca0 + 3][ra1] = aP1.w;
    Bs[0][ca0 + 0][ra0] = bP0.x; Bs[0][ca0 + 1][ra0] = bP0.y;
    Bs[0][ca0 + 2][ra0] = bP0.z; Bs[0][ca0 + 3][ra0] = bP0.w;
    Bs[0][ca0 + 0][ra1] = bP1.x; Bs[0][ca0 + 1][ra1] = bP1.y;
    Bs[0][ca0 + 2][ra1] = bP1.z; Bs[0][ca0 + 3][ra1] = bP1.w;
    __syncthreads();

    #pragma unroll
    for (int k0 = 0; k0 < K; k0 += 16) {
        constexpr int NIT = K / 16;
        const int it = k0 / 16;
        const int p  = it & 1;
        const bool hasNext = (it + 1) < NIT;

        // prefetch next tile (LDG latency hidden behind the compute below)
        if (hasNext) {
            const int kn = k0 + 16;
            aP0 = *(const float4*)(Arow0 + kn);
            aP1 = *(const float4*)(Arow1 + kn);
            bP0 = *(const float4*)(Brow0 + kn);
            bP1 = *(const float4*)(Brow1 + kn);
        }

        #pragma unroll
        for (int k = 0; k < 16; ++k) {
            *(float4*)&ar[0] = *(const float4*)&As[p][k][ty * 8];
            *(float4*)&ar[4] = *(const float4*)&As[p][k][ty * 8 + 4];
            *(float4*)&br[0] = *(const float4*)&Bs[p][k][tx * 8];
            *(float4*)&br[4] = *(const float4*)&Bs[p][k][tx * 8 + 4];
            #pragma unroll
            for (int i = 0; i < 8; ++i)
                #pragma unroll
                for (int j = 0; j < 8; ++j)
                    acc[i][j] = fmaf(ar[i], br[j], acc[i][j]);
        }

        if (hasNext) {
            const int q = p ^ 1;     // safe: buf q last read before previous barrier
            As[q][ca0 + 0][ra0] = aP0.x; As[q][ca0 + 1][ra0] = aP0.y;
            As[q][ca0 + 2][ra0] = aP0.z; As[q][ca0 + 3][ra0] = aP0.w;
            As[q][ca0 + 0][ra1] = aP1.x; As[q][ca0 + 1][ra1] = aP1.y;
            As[q][ca0 + 2][ra1] = aP1.z; As[q][ca0 + 3][ra1] = aP1.w;
            Bs[q][ca0 + 0][ra0] = bP0.x; Bs[q][ca0 + 1][ra0] = bP0.y;
            Bs[q][ca0 + 2][ra0] = bP0.z; Bs[q][ca0 + 3][ra0] = bP0.w;
            Bs[q][ca0 + 0][ra1] = bP1.x; Bs[q][ca0 + 1][ra1] = bP1.y;
            Bs[q][ca0 + 2][ra1] = bP1.z; Bs[q][ca0 + 3][ra1] = bP1.w;
            __syncthreads();
        }
    }

    // bias (per output column)
    float bv[8];
    #pragma unroll
    for (int j = 0; j < 8; ++j) {
        int c = colBase + tx * 8 + j;
        float b = bias1 ? bias1[c] : 0.f;
        if (bias2) b += bias2[c];
        bv[j] = b;
    }

    #pragma unroll
    for (int i = 0; i < 8; ++i) {
        int r = rowBase + ty * 8 + i;
        int c = colBase + tx * 8;
        float4 o0, o1;
        o0.x = acc[i][0] + bv[0]; o0.y = acc[i][1] + bv[1];
        o0.z = acc[i][2] + bv[2]; o0.w = acc[i][3] + bv[3];
        o1.x = acc[i][4] + bv[4]; o1.y = acc[i][5] + bv[5];
        o1.z = acc[i][6] + bv[6]; o1.w = acc[i][7] + bv[7];
        *(float4*)(C + (size_t)r * Nn + c)     = o0;
        *(float4*)(C + (size_t)r * Nn + c + 4) = o1;
    }

    // fused GATv2 score epilogue: only rows < NN matter (reference's flat
    // indexing pulls scores from the (b=0,v=0) block only).
    if (SCORES) {
        if (rowBase < NN) {
            const int head = tx >> 2;              // cols tx*8..tx*8+7 lie in one head
            // att layout: [HEADS][2*OUT_F]; src weights [0,32), dst [32,64)
            float aw_s[8], aw_d[8];
            #pragma unroll
            for (int j = 0; j < 8; ++j) {
                int coff = ((tx & 3) << 3) + j;    // 0..31 within head
                aw_s[j] = att[head * 64 + coff];
                aw_d[j] = att[head * 64 + 32 + coff];
            }
            #pragma unroll
            for (int i = 0; i < 8; ++i) {
                int r = rowBase + ty * 8 + i;
                float ps = 0.f, pd = 0.f;
                #pragma unroll
                for (int j = 0; j < 8; ++j) {
                    float hv = acc[i][j];          // bias1==nullptr at this call site
                    float lr = hv > 0.f ? hv : NEG_SLOPE * hv;
                    ps = fmaf(aw_s[j], lr, ps);
                    pd = fmaf(aw_d[j], lr, pd);
                }
                // reduce over the 4 threads (tx & 3) sharing this head+row;
                // they are adjacent lanes of the same warp
                #pragma unroll
                for (int o = 1; o <= 2; o <<= 1) {
                    ps += __shfl_xor_sync(0xffffffffu, ps, o);
                    pd += __shfl_xor_sync(0xffffffffu, pd, o);
                }
                if ((tx & 3) == 0 && r < NN) {
                    g_ssrc[r * HEADS + head] = ps;
                    g_sdst[r * HEADS + head] = pd;
                }
            }
        }
    }
}

// ---------------- CSR build --------------------------------------------------
__global__ void count_edges(const void* __restrict__ ei) {
    int e = blockIdx.x * blockDim.x + threadIdx.x;
    if (e < EE) atomicAdd(&g_deg[edge_at(ei, EE + e)], 1);
}

// Adds the +1 self-loop itself and resets g_deg to zero for the next replay
// (graph-capture determinism: deg is zero at module load, count->scan->reset).
__global__ __launch_bounds__(1024) void scan_deg() {
    __shared__ int sums[1024];
    int tid = threadIdx.x;
    int base = tid * 4;
    int local[4];
    int s = 0;
    #pragma unroll
    for (int j = 0; j < 4; ++j) {
        local[j] = (base + j < NTOT) ? (g_deg[base + j] + 1) : 0;
        s += local[j];
    }
    #pragma unroll
    for (int j = 0; j < 4; ++j)
        if (base + j < NTOT) g_deg[base + j] = 0;
    sums[tid] = s;
    __syncthreads();
    for (int off = 1; off < 1024; off <<= 1) {
        int v = (tid >= off) ? sums[tid - off] : 0;
        __syncthreads();
        sums[tid] += v;
        __syncthreads();
    }
    int run = tid ? sums[tid - 1] : 0;
    #pragma unroll
    for (int j = 0; j < 4; ++j) {
        if (base + j < NTOT) {
            g_off[base + j] = run;
            g_cur[base + j] = run;
            run += local[j];
        }
    }
    if (tid == 1023) g_off[NTOT] = sums[1023];
}

__global__ void fill_csr(const void* __restrict__ ei) {
    int e = blockIdx.x * blockDim.x + threadIdx.x;
    if (e >= ETOT) return;
    int src, dst;
    if (e < EE) { src = edge_at(ei, e); dst = edge_at(ei, EE + e); }
    else        { src = dst = e - EE; }
    int pos = atomicAdd(&g_cur[dst], 1);
    g_csr[pos] = src;
}

// ---------------- GAT softmax + aggregate (one block per dst) ----------------
__global__ __launch_bounds__(128) void gat_aggregate()
{
    int d = blockIdx.x;              // 0..3999
    int tid = threadIdx.x;           // thread owns feature f=tid
    int hh = tid >> 5, lane = tid & 31;
    int b = d / NN, dloc = d - b * NN;
    int beg = g_off[d], end = g_off[d + 1];

    __shared__ float m[HEADS], denom[HEADS];
    float sdst = g_sdst[d * HEADS + hh];

    // per-head max (warp hh handles head hh, lanes over edges)
    float lmax = -1e30f;
    for (int j = beg + lane; j < end; j += 32)
        lmax = fmaxf(lmax, g_ssrc[g_csr[j] * HEADS + hh] + sdst);
    #pragma unroll
    for (int o = 16; o; o >>= 1)
        lmax = fmaxf(lmax, __shfl_xor_sync(0xffffffffu, lmax, o));
    if (lane == 0) m[hh] = lmax;
    __syncthreads();

    float mh = m[hh];
    float lsum = 0.f;
    for (int j = beg + lane; j < end; j += 32)
        lsum += __expf(g_ssrc[g_csr[j] * HEADS + hh] + sdst - mh);
    #pragma unroll
    for (int o = 16; o; o >>= 1)
        lsum += __shfl_xor_sync(0xffffffffu, lsum, o);
    if (lane == 0) denom[hh] = lsum + 1e-16f;
    __syncthreads();

    float dh = denom[hh];
    float acc0 = 0.f, acc1 = 0.f, acc2 = 0.f, acc3 = 0.f;
    const int blo = b * NN, bhi = blo + NN;
    const size_t vstride = (size_t)NN * DD;   // view stride in floats
    for (int j = beg; j < end; ++j) {
        int src = g_csr[j];
        if (src >= blo && src < bhi) {     // only same-block srcs have nonzero rows
            float alpha = __expf(g_ssrc[src * HEADS + hh] + sdst - mh) / dh;
            const float* hp = g_h + ((size_t)(b * VV) * NN + (src - blo)) * DD + tid;
            acc0 = fmaf(alpha, hp[0],           acc0);
            acc1 = fmaf(alpha, hp[vstride],     acc1);
            acc2 = fmaf(alpha, hp[2 * vstride], acc2);
            acc3 = fmaf(alpha, hp[3 * vstride], acc3);
        }
    }
    size_t ob = ((size_t)(b * VV) * NN + dloc) * DD + tid;
    g_hgat[ob]               = acc0;
    g_hgat[ob + vstride]     = acc1;
    g_hgat[ob + 2 * vstride] = acc2;
    g_hgat[ob + 3 * vstride] = acc3;
}

// ---------------- per-node 4-view MHA (warp = head) --------------------------
__global__ __launch_bounds__(128) void mha_attn()
{
    int nid = blockIdx.x;            // 0..3999 (= b*N+n)
    int b = nid / NN, n = nid - b * NN;
    int tid = threadIdx.x;
    int hh = tid >> 5, lane = tid & 31;

    float q[4], k[4], v[4];
    #pragma unroll
    for (int vv = 0; vv < 4; ++vv) {
        size_t r = ((size_t)(b * VV + vv) * NN + n) * 384;
        q[vv] = g_qkv[r +       hh * 32 + lane];
        k[vv] = g_qkv[r + 128 + hh * 32 + lane];
        v[vv] = g_qkv[r + 256 + hh * 32 + lane];
    }

    const float inv_sqrt = 0.1767766952966369f; // 1/sqrt(32)
    float s[4][4];
    #pragma unroll
    for (int qv = 0; qv < 4; ++qv)
        #pragma unroll
        for (int kv = 0; kv < 4; ++kv) {
            float p = q[qv] * k[kv];
            #pragma unroll
            for (int o = 16; o; o >>= 1)
                p += __shfl_xor_sync(0xffffffffu, p, o);
            s[qv][kv] = p * inv_sqrt;
        }

    #pragma unroll
    for (int qv = 0; qv < 4; ++qv) {
        float mx = fmaxf(fmaxf(s[qv][0], s[qv][1]), fmaxf(s[qv][2], s[qv][3]));
        float e0 = __expf(s[qv][0] - mx), e1 = __expf(s[qv][1] - mx);
        float e2 = __expf(s[qv][2] - mx), e3 = __expf(s[qv][3] - mx);
        float inv = 1.f / (e0 + e1 + e2 + e3);
        float o = (e0 * v[0] + e1 * v[1] + e2 * v[2] + e3 * v[3]) * inv;
        g_ao[((size_t)(b * VV + qv) * NN + n) * DD + hh * 32 + lane] = o;
    }
}

// ---------------- launch -----------------------------------------------------
extern "C" void kernel_launch(void* const* d_in, const int* in_sizes, int n_in,
                              void* d_out, int out_size)
{
    const float* x          = (const float*)d_in[0];
    const float* W          = (const float*)d_in[1];
    const float* att        = (const float*)d_in[2];
    const float* in_proj_w  = (const float*)d_in[3];
    const float* in_proj_b  = (const float*)d_in[4];
    const float* out_proj_w = (const float*)d_in[5];
    const float* out_proj_b = (const float*)d_in[6];
    const float* bias       = (const float*)d_in[7];
    const void*  edge_index = d_in[8];          // int32 or int64, detected on device
    float* out = (float*)d_out;

    float* h    = nullptr; cudaGetSymbolAddress((void**)&h,    g_h);
    float* hgat = nullptr; cudaGetSymbolAddress((void**)&hgat, g_hgat);
    float* qkv  = nullptr; cudaGetSymbolAddress((void**)&qkv,  g_qkv);
    float* ao   = nullptr; cudaGetSymbolAddress((void**)&ao,   g_ao);

    // 0) edge dtype detection (device-side, deterministic)
    detect_dtype<<<1, 32>>>((const unsigned int*)edge_index);

    // 1) h = x @ W^T  [16000,64]x[128,64]^T -> [16000,128], fused score epilogue
    gemm_tn<IN_F, true><<<dim3(1, 125), 256>>>(x, W, nullptr, nullptr, att, h, DD);

    // 2) CSR by dst (deg starts zero; scan adds self-loop and resets deg)
    count_edges<<<(EE + 255) / 256, 256>>>(edge_index);
    scan_deg<<<1, 1024>>>();
    fill_csr<<<(ETOT + 255) / 256, 256>>>(edge_index);

    // 3) segment softmax + aggregate
    gat_aggregate<<<NTOT, 128>>>();

    // 4) in_proj: qkv = h_gat @ in_proj_w^T + b  [16000,128]x[384,128]^T
    gemm_tn<DD, false><<<dim3(3, 125), 256>>>(hgat, in_proj_w, in_proj_b, nullptr, nullptr, qkv, 384);

    // 5) per-node MHA over 4 views
    mha_attn<<<NTOT, 128>>>();

    // 6) out_proj + out_proj_b + bias, written straight to d_out
    gemm_tn<DD, false><<<dim3(1, 125), 256>>>(ao, out_proj_w, out_proj_b, bias, nullptr, out, DD);
}

// round 10
// speedup vs baseline: 1.3192x; 1.3192x over previous
#include <cuda_runtime.h>
#include <cuda_bf16.h>
#include <cstdint>
#include <cstring>

// Problem constants
#define BB 4
#define VV 4
#define NN 1000
#define IN_F 64
#define HEADS 4
#define OUT_F 32
#define DD 128           // HEADS*OUT_F
#define EE 64000
#define NTOT 4000        // B*N
#define ETOT 68000       // E + self loops
#define ROWS 16000       // B*V*N
#define NEG_SLOPE 0.2f

// ---------------- scratch (static device globals; no allocation) -------------
__device__ float g_h[ROWS * DD];        // GAT linear output, row=(b*4+v)*1000+n
__device__ float g_hgat[ROWS * DD];     // GAT aggregated output
__device__ float g_qkv[ROWS * 384];     // in_proj output
__device__ float g_ao[ROWS * DD];       // attention output
__device__ float g_ssrc[NTOT * HEADS];  // zero-init; only i<NN ever written
__device__ float g_sdst[NTOT * HEADS];  // zero-init; only i<NN ever written
__device__ int   g_deg[NTOT];           // zero at load; scan resets to zero each run
__device__ int   g_off[NTOT + 1];
__device__ int   g_cur[NTOT];
__device__ int   g_csr[ETOT];

// unpack packed f32x2
__device__ __forceinline__ float2 up2(unsigned long long v) {
    float2 f; memcpy(&f, &v, 8); return f;
}

// ---------------- tiled fp32 GEMM: C[M][Nn] = A[M][K] @ B[Nn][K]^T -----------
// 128x128 tile, 256 threads, 8x8 microtile, K-step 16, K a template constant.
// Inner product uses packed fma.rn.f32x2 (FFMA2): 32 FMA-pipe instr per
// thread-k instead of 64; IEEE fp32 lanewise, bit-compatible accumulation.
// Double-buffered smem: one barrier per mainloop iteration.
// SCORES: fused GATv2 per-node score epilogue (valid only when grid.x==1 so a
// CTA owns full 128-wide rows; writes g_ssrc/g_sdst for rows < NN).
// Requires: M % 128 == 0, Nn % 128 == 0, K % 16 == 0 (true for all call sites).
template <int K, bool SCORES>
__global__ __launch_bounds__(256) void gemm_tn(
    const float* __restrict__ A, const float* __restrict__ Bm,
    const float* __restrict__ bias1, const float* __restrict__ bias2,
    const float* __restrict__ att,
    float* __restrict__ C, int Nn)
{
    __shared__ float As[2][16][132];   // [buf][k][m], padded (132 % 32 == 4)
    __shared__ float Bs[2][16][132];   // [buf][k][n]; row base 16B-aligned (528B)
    const int tid = threadIdx.x;
    const int tx = tid & 15;        // 0..15 -> col group (8 cols)
    const int ty = tid >> 4;        // 0..15 -> row group (8 rows)
    const int rowBase = blockIdx.y * 128;
    const int colBase = blockIdx.x * 128;

    // per-thread load coordinates: two A rows, two B rows, same k-quad
    const int ra0 = tid >> 2;            // 0..63
    const int ra1 = ra0 + 64;            // 64..127
    const int ca0 = (tid & 3) << 2;      // 0,4,8,12

    unsigned long long acc2[8][4] = {};  // [i][jp] -> cols (2jp, 2jp+1), fp32x2
    float ar[8];
    unsigned long long brp[4];
    float4 aP0, aP1, bP0, bP1;

    const float* Arow0 = A  + (size_t)(rowBase + ra0) * K + ca0;
    const float* Arow1 = A  + (size_t)(rowBase + ra1) * K + ca0;
    const float* Brow0 = Bm + (size_t)(colBase + ra0) * K + ca0;
    const float* Brow1 = Bm + (size_t)(colBase + ra1) * K + ca0;

    // prologue: prefetch tile k0=0 and commit to buffer 0
    aP0 = *(const float4*)(Arow0);
    aP1 = *(const float4*)(Arow1);
    bP0 = *(const float4*)(Brow0);
    bP1 = *(const float4*)(Brow1);
    As[0][ca0 + 0][ra0] = aP0.x; As[0][ca0 + 1][ra0] = aP0.y;
    As[0][ca0 + 2][ra0] = aP0.z; As[0][ca0 + 3][ra0] = aP0.w;
    As[0][ca0 + 0][ra1] = aP1.x; As[0][ca0 + 1][ra1] = aP1.y;
    As[0][ca0 + 2][ra1] = aP1.z; As[0][ca0 + 3][ra1] = aP1.w;
    Bs[0][ca0 + 0][ra0] = bP0.x; Bs[0][ca0 + 1][ra0] = bP0.y;
    Bs[0][ca0 + 2][ra0] = bP0.z; Bs[0][ca0 + 3][ra0] = bP0.w;
    Bs[0][ca0 + 0][ra1] = bP1.x; Bs[0][ca0 + 1][ra1] = bP1.y;
    Bs[0][ca0 + 2][ra1] = bP1.z; Bs[0][ca0 + 3][ra1] = bP1.w;
    __syncthreads();

    #pragma unroll
    for (int k0 = 0; k0 < K; k0 += 16) {
        constexpr int NIT = K / 16;
        const int it = k0 / 16;
        const int p  = it & 1;
        const bool hasNext = (it + 1) < NIT;

        // prefetch next tile (LDG latency hidden behind the compute below)
        if (hasNext) {
            const int kn = k0 + 16;
            aP0 = *(const float4*)(Arow0 + kn);
            aP1 = *(const float4*)(Arow1 + kn);
            bP0 = *(const float4*)(Brow0 + kn);
            bP1 = *(const float4*)(Brow1 + kn);
        }

        #pragma unroll
        for (int k = 0; k < 16; ++k) {
            *(float4*)&ar[0] = *(const float4*)&As[p][k][ty * 8];
            *(float4*)&ar[4] = *(const float4*)&As[p][k][ty * 8 + 4];
            ulonglong2 b01 = *(const ulonglong2*)&Bs[p][k][tx * 8];
            ulonglong2 b23 = *(const ulonglong2*)&Bs[p][k][tx * 8 + 4];
            brp[0] = b01.x; brp[1] = b01.y; brp[2] = b23.x; brp[3] = b23.y;
            #pragma unroll
            for (int i = 0; i < 8; ++i) {
                unsigned int au = __float_as_uint(ar[i]);
                unsigned long long arp;
                asm("mov.b64 %0, {%1, %1};" : "=l"(arp) : "r"(au));
                #pragma unroll
                for (int jp = 0; jp < 4; ++jp)
                    asm("fma.rn.f32x2 %0, %1, %2, %0;"
                        : "+l"(acc2[i][jp]) : "l"(arp), "l"(brp[jp]));
            }
        }

        if (hasNext) {
            const int q = p ^ 1;     // safe: buf q last read before previous barrier
            As[q][ca0 + 0][ra0] = aP0.x; As[q][ca0 + 1][ra0] = aP0.y;
            As[q][ca0 + 2][ra0] = aP0.z; As[q][ca0 + 3][ra0] = aP0.w;
            As[q][ca0 + 0][ra1] = aP1.x; As[q][ca0 + 1][ra1] = aP1.y;
            As[q][ca0 + 2][ra1] = aP1.z; As[q][ca0 + 3][ra1] = aP1.w;
            Bs[q][ca0 + 0][ra0] = bP0.x; Bs[q][ca0 + 1][ra0] = bP0.y;
            Bs[q][ca0 + 2][ra0] = bP0.z; Bs[q][ca0 + 3][ra0] = bP0.w;
            Bs[q][ca0 + 0][ra1] = bP1.x; Bs[q][ca0 + 1][ra1] = bP1.y;
            Bs[q][ca0 + 2][ra1] = bP1.z; Bs[q][ca0 + 3][ra1] = bP1.w;
            __syncthreads();
        }
    }

    // bias (per output column)
    float bv[8];
    #pragma unroll
    for (int j = 0; j < 8; ++j) {
        int c = colBase + tx * 8 + j;
        float b = bias1 ? bias1[c] : 0.f;
        if (bias2) b += bias2[c];
        bv[j] = b;
    }

    #pragma unroll
    for (int i = 0; i < 8; ++i) {
        int r = rowBase + ty * 8 + i;
        int c = colBase + tx * 8;
        float2 p0 = up2(acc2[i][0]), p1 = up2(acc2[i][1]);
        float2 p2 = up2(acc2[i][2]), p3 = up2(acc2[i][3]);
        float4 o0, o1;
        o0.x = p0.x + bv[0]; o0.y = p0.y + bv[1];
        o0.z = p1.x + bv[2]; o0.w = p1.y + bv[3];
        o1.x = p2.x + bv[4]; o1.y = p2.y + bv[5];
        o1.z = p3.x + bv[6]; o1.w = p3.y + bv[7];
        *(float4*)(C + (size_t)r * Nn + c)     = o0;
        *(float4*)(C + (size_t)r * Nn + c + 4) = o1;
    }

    // fused GATv2 score epilogue: only rows < NN matter (reference's flat
    // indexing pulls scores from the (b=0,v=0) block only).
    if (SCORES) {
        if (rowBase < NN) {
            const int head = tx >> 2;              // cols tx*8..tx*8+7 lie in one head
            // att layout: [HEADS][2*OUT_F]; src weights [0,32), dst [32,64)
            float aw_s[8], aw_d[8];
            #pragma unroll
            for (int j = 0; j < 8; ++j) {
                int coff = ((tx & 3) << 3) + j;    // 0..31 within head
                aw_s[j] = att[head * 64 + coff];
                aw_d[j] = att[head * 64 + 32 + coff];
            }
            #pragma unroll
            for (int i = 0; i < 8; ++i) {
                int r = rowBase + ty * 8 + i;
                float ps = 0.f, pd = 0.f;
                #pragma unroll
                for (int j = 0; j < 8; ++j) {
                    float2 pr = up2(acc2[i][j >> 1]);
                    float hv = (j & 1) ? pr.y : pr.x;  // bias1==nullptr here
                    float lr = hv > 0.f ? hv : NEG_SLOPE * hv;
                    ps = fmaf(aw_s[j], lr, ps);
                    pd = fmaf(aw_d[j], lr, pd);
                }
                // reduce over the 4 adjacent lanes (tx & 3) sharing head+row
                #pragma unroll
                for (int o = 1; o <= 2; o <<= 1) {
                    ps += __shfl_xor_sync(0xffffffffu, ps, o);
                    pd += __shfl_xor_sync(0xffffffffu, pd, o);
                }
                if ((tx & 3) == 0 && r < NN) {
                    g_ssrc[r * HEADS + head] = ps;
                    g_sdst[r * HEADS + head] = pd;
                }
            }
        }
    }
}

// ---------------- CSR build --------------------------------------------------
// Edge dtype detection is done per-block: if edge_index is int64 (values in
// [0,4000)), every odd 32-bit word of the first 512 entries is the zero high
// half; if int32, those words are real ids ~U[0,4000) and P(all zero) == 0.
__device__ __forceinline__ int block_edge_is32(const unsigned int* __restrict__ w) {
    unsigned int any = 0;
    for (int i = threadIdx.x; i < 512; i += blockDim.x)
        any |= w[2 * i + 1];
    return __syncthreads_or(any != 0u);   // nonzero -> int32
}

__global__ void count_edges(const unsigned int* __restrict__ w) {
    const int is32 = block_edge_is32(w);
    int e = blockIdx.x * blockDim.x + threadIdx.x;
    if (e < EE) {
        int dst = is32 ? ((const int*)w)[EE + e]
                       : (int)((const long long*)w)[EE + e];
        atomicAdd(&g_deg[dst], 1);
    }
}

// Warp-shuffle scan (2 barriers). Adds the +1 self-loop itself and resets
// g_deg to zero for the next replay (graph determinism: zero at load,
// count -> scan -> reset).
__global__ __launch_bounds__(1024) void scan_deg() {
    __shared__ int wsum[32];
    const int tid = threadIdx.x;
    const int lane = tid & 31, wid = tid >> 5;
    const int base = tid * 4;
    int l[4], s = 0;
    #pragma unroll
    for (int j = 0; j < 4; ++j) {
        int idx = base + j;
        l[j] = (idx < NTOT) ? (g_deg[idx] + 1) : 0;
        s += l[j];
    }
    #pragma unroll
    for (int j = 0; j < 4; ++j)
        if (base + j < NTOT) g_deg[base + j] = 0;

    int sc = s;   // inclusive scan over per-thread sums
    #pragma unroll
    for (int o = 1; o < 32; o <<= 1) {
        int v = __shfl_up_sync(0xffffffffu, sc, o);
        if (lane >= o) sc += v;
    }
    if (lane == 31) wsum[wid] = sc;
    __syncthreads();
    if (wid == 0) {
        int ws = wsum[lane];
        #pragma unroll
        for (int o = 1; o < 32; o <<= 1) {
            int v = __shfl_up_sync(0xffffffffu, ws, o);
            if (lane >= o) ws += v;
        }
        wsum[lane] = ws;
    }
    __syncthreads();
    int exc = sc - s + (wid ? wsum[wid - 1] : 0);
    #pragma unroll
    for (int j = 0; j < 4; ++j) {
        int idx = base + j;
        if (idx < NTOT) { g_off[idx] = exc; g_cur[idx] = exc; }
        exc += l[j];
    }
    if (tid == 1023) g_off[NTOT] = wsum[31];
}

__global__ void fill_csr(const unsigned int* __restrict__ w) {
    const int is32 = block_edge_is32(w);
    int e = blockIdx.x * blockDim.x + threadIdx.x;
    if (e >= ETOT) return;
    int src, dst;
    if (e < EE) {
        if (is32) { src = ((const int*)w)[e]; dst = ((const int*)w)[EE + e]; }
        else      { src = (int)((const long long*)w)[e];
                    dst = (int)((const long long*)w)[EE + e]; }
    } else {
        src = dst = e - EE;
    }
    int pos = atomicAdd(&g_cur[dst], 1);
    g_csr[pos] = src;
}

// ---------------- GAT softmax + aggregate (one block per dst) ----------------
__global__ __launch_bounds__(128) void gat_aggregate()
{
    int d = blockIdx.x;              // 0..3999
    int tid = threadIdx.x;           // thread owns feature f=tid
    int hh = tid >> 5, lane = tid & 31;
    int b = d / NN, dloc = d - b * NN;
    int beg = g_off[d], end = g_off[d + 1];

    __shared__ float m[HEADS], denom[HEADS];
    float sdst = g_sdst[d * HEADS + hh];

    // per-head max (warp hh handles head hh, lanes over edges)
    float lmax = -1e30f;
    for (int j = beg + lane; j < end; j += 32)
        lmax = fmaxf(lmax, g_ssrc[g_csr[j] * HEADS + hh] + sdst);
    #pragma unroll
    for (int o = 16; o; o >>= 1)
        lmax = fmaxf(lmax, __shfl_xor_sync(0xffffffffu, lmax, o));
    if (lane == 0) m[hh] = lmax;
    __syncthreads();

    float mh = m[hh];
    float lsum = 0.f;
    for (int j = beg + lane; j < end; j += 32)
        lsum += __expf(g_ssrc[g_csr[j] * HEADS + hh] + sdst - mh);
    #pragma unroll
    for (int o = 16; o; o >>= 1)
        lsum += __shfl_xor_sync(0xffffffffu, lsum, o);
    if (lane == 0) denom[hh] = lsum + 1e-16f;
    __syncthreads();

    float dh = denom[hh];
    float acc0 = 0.f, acc1 = 0.f, acc2 = 0.f, acc3 = 0.f;
    const int blo = b * NN, bhi = blo + NN;
    const size_t vstride = (size_t)NN * DD;   // view stride in floats
    for (int j = beg; j < end; ++j) {
        int src = g_csr[j];
        if (src >= blo && src < bhi) {     // only same-block srcs have nonzero rows
            float alpha = __expf(g_ssrc[src * HEADS + hh] + sdst - mh) / dh;
            const float* hp = g_h + ((size_t)(b * VV) * NN + (src - blo)) * DD + tid;
            acc0 = fmaf(alpha, hp[0],           acc0);
            acc1 = fmaf(alpha, hp[vstride],     acc1);
            acc2 = fmaf(alpha, hp[2 * vstride], acc2);
            acc3 = fmaf(alpha, hp[3 * vstride], acc3);
        }
    }
    size_t ob = ((size_t)(b * VV) * NN + dloc) * DD + tid;
    g_hgat[ob]               = acc0;
    g_hgat[ob + vstride]     = acc1;
    g_hgat[ob + 2 * vstride] = acc2;
    g_hgat[ob + 3 * vstride] = acc3;
}

// ---------------- per-node 4-view MHA (warp = head) --------------------------
__global__ __launch_bounds__(128) void mha_attn()
{
    int nid = blockIdx.x;            // 0..3999 (= b*N+n)
    int b = nid / NN, n = nid - b * NN;
    int tid = threadIdx.x;
    int hh = tid >> 5, lane = tid & 31;

    float q[4], k[4], v[4];
    #pragma unroll
    for (int vv = 0; vv < 4; ++vv) {
        size_t r = ((size_t)(b * VV + vv) * NN + n) * 384;
        q[vv] = g_qkv[r +       hh * 32 + lane];
        k[vv] = g_qkv[r + 128 + hh * 32 + lane];
        v[vv] = g_qkv[r + 256 + hh * 32 + lane];
    }

    const float inv_sqrt = 0.1767766952966369f; // 1/sqrt(32)
    float s[4][4];
    #pragma unroll
    for (int qv = 0; qv < 4; ++qv)
        #pragma unroll
        for (int kv = 0; kv < 4; ++kv) {
            float p = q[qv] * k[kv];
            #pragma unroll
            for (int o = 16; o; o >>= 1)
                p += __shfl_xor_sync(0xffffffffu, p, o);
            s[qv][kv] = p * inv_sqrt;
        }

    #pragma unroll
    for (int qv = 0; qv < 4; ++qv) {
        float mx = fmaxf(fmaxf(s[qv][0], s[qv][1]), fmaxf(s[qv][2], s[qv][3]));
        float e0 = __expf(s[qv][0] - mx), e1 = __expf(s[qv][1] - mx);
        float e2 = __expf(s[qv][2] - mx), e3 = __expf(s[qv][3] - mx);
        float inv = 1.f / (e0 + e1 + e2 + e3);
        float o = (e0 * v[0] + e1 * v[1] + e2 * v[2] + e3 * v[3]) * inv;
        g_ao[((size_t)(b * VV + qv) * NN + n) * DD + hh * 32 + lane] = o;
    }
}

// ---------------- launch -----------------------------------------------------
extern "C" void kernel_launch(void* const* d_in, const int* in_sizes, int n_in,
                              void* d_out, int out_size)
{
    const float* x          = (const float*)d_in[0];
    const float* W          = (const float*)d_in[1];
    const float* att        = (const float*)d_in[2];
    const float* in_proj_w  = (const float*)d_in[3];
    const float* in_proj_b  = (const float*)d_in[4];
    const float* out_proj_w = (const float*)d_in[5];
    const float* out_proj_b = (const float*)d_in[6];
    const float* bias       = (const float*)d_in[7];
    const unsigned int* edge_index = (const unsigned int*)d_in[8]; // int32 or int64
    float* out = (float*)d_out;

    float* h    = nullptr; cudaGetSymbolAddress((void**)&h,    g_h);
    float* hgat = nullptr; cudaGetSymbolAddress((void**)&hgat, g_hgat);
    float* qkv  = nullptr; cudaGetSymbolAddress((void**)&qkv,  g_qkv);
    float* ao   = nullptr; cudaGetSymbolAddress((void**)&ao,   g_ao);

    // 1) h = x @ W^T  [16000,64]x[128,64]^T -> [16000,128], fused score epilogue
    gemm_tn<IN_F, true><<<dim3(1, 125), 256>>>(x, W, nullptr, nullptr, att, h, DD);

    // 2) CSR by dst (deg starts zero; scan adds self-loop and resets deg)
    count_edges<<<(EE + 255) / 256, 256>>>(edge_index);
    scan_deg<<<1, 1024>>>();
    fill_csr<<<(ETOT + 255) / 256, 256>>>(edge_index);

    // 3) segment softmax + aggregate
    gat_aggregate<<<NTOT, 128>>>();

    // 4) in_proj: qkv = h_gat @ in_proj_w^T + b  [16000,128]x[384,128]^T
    gemm_tn<DD, false><<<dim3(3, 125), 256>>>(hgat, in_proj_w, in_proj_b, nullptr, nullptr, qkv, 384);

    // 5) per-node MHA over 4 views
    mha_attn<<<NTOT, 128>>>();

    // 6) out_proj + out_proj_b + bias, written straight to d_out
    gemm_tn<DD, false><<<dim3(1, 125), 256>>>(ao, out_proj_w, out_proj_b, bias, nullptr, out, DD);
}

// round 12
// speedup vs baseline: 1.3711x; 1.0393x over previous
#include <cuda_runtime.h>
#include <cuda_bf16.h>
#include <cstdint>
#include <cstring>

// Problem constants
#define BB 4
#define VV 4
#define NN 1000
#define IN_F 64
#define HEADS 4
#define OUT_F 32
#define DD 128           // HEADS*OUT_F
#define EE 64000
#define NTOT 4000        // B*N
#define ETOT 68000       // E + self loops
#define ROWS 16000       // B*V*N
#define NEG_SLOPE 0.2f

// ---------------- scratch (static device globals; no allocation) -------------
__device__ float g_h[ROWS * DD];        // GAT linear output, row=(b*4+v)*1000+n
__device__ float g_hgat[ROWS * DD];     // GAT aggregated output
__device__ float g_qkv[ROWS * 384];     // in_proj output
__device__ float g_ao[ROWS * DD];       // attention output
__device__ float g_esrc[NTOT * HEADS];  // exp(s_src); [NN..) set to 1.0 by scan_deg
__device__ int   g_deg[NTOT];           // zero at load; scan resets to zero each run
__device__ int   g_off[NTOT + 1];
__device__ int   g_cur[NTOT];
__device__ int   g_csr[ETOT];

// unpack packed f32x2
__device__ __forceinline__ float2 up2(unsigned long long v) {
    float2 f; memcpy(&f, &v, 8); return f;
}

// ---------------- tiled fp32 GEMM: C[M][Nn] = A[M][K] @ B[Nn][K]^T -----------
// 128x128 tile, 256 threads, 8x8 microtile, K-step 16, K a template constant.
// Inner product uses packed fma.rn.f32x2 (FFMA2). Double-buffered smem.
// SCORES: fused GATv2 score epilogue writing g_esrc = exp(s_src) for rows < NN
// (softmax over a segment is invariant to the per-dst s_dst term and to max
// subtraction, so only exp(s_src) is needed). Valid only when grid.x==1.
// Requires: M % 128 == 0, Nn % 128 == 0, K % 16 == 0 (true for all call sites).
template <int K, bool SCORES>
__global__ __launch_bounds__(256) void gemm_tn(
    const float* __restrict__ A, const float* __restrict__ Bm,
    const float* __restrict__ bias1, const float* __restrict__ bias2,
    const float* __restrict__ att,
    float* __restrict__ C, int Nn)
{
    __shared__ float As[2][16][132];   // [buf][k][m], padded (132 % 32 == 4)
    __shared__ float Bs[2][16][132];   // [buf][k][n]; row base 16B-aligned (528B)
    const int tid = threadIdx.x;
    const int tx = tid & 15;        // 0..15 -> col group (8 cols)
    const int ty = tid >> 4;        // 0..15 -> row group (8 rows)
    const int rowBase = blockIdx.y * 128;
    const int colBase = blockIdx.x * 128;

    // per-thread load coordinates: two A rows, two B rows, same k-quad
    const int ra0 = tid >> 2;            // 0..63
    const int ra1 = ra0 + 64;            // 64..127
    const int ca0 = (tid & 3) << 2;      // 0,4,8,12

    unsigned long long acc2[8][4] = {};  // [i][jp] -> cols (2jp, 2jp+1), fp32x2
    float ar[8];
    unsigned long long brp[4];
    float4 aP0, aP1, bP0, bP1;

    const float* Arow0 = A  + (size_t)(rowBase + ra0) * K + ca0;
    const float* Arow1 = A  + (size_t)(rowBase + ra1) * K + ca0;
    const float* Brow0 = Bm + (size_t)(colBase + ra0) * K + ca0;
    const float* Brow1 = Bm + (size_t)(colBase + ra1) * K + ca0;

    // prologue: prefetch tile k0=0 and commit to buffer 0
    aP0 = *(const float4*)(Arow0);
    aP1 = *(const float4*)(Arow1);
    bP0 = *(const float4*)(Brow0);
    bP1 = *(const float4*)(Brow1);
    As[0][ca0 + 0][ra0] = aP0.x; As[0][ca0 + 1][ra0] = aP0.y;
    As[0][ca0 + 2][ra0] = aP0.z; As[0][ca0 + 3][ra0] = aP0.w;
    As[0][ca0 + 0][ra1] = aP1.x; As[0][ca0 + 1][ra1] = aP1.y;
    As[0][ca0 + 2][ra1] = aP1.z; As[0][ca0 + 3][ra1] = aP1.w;
    Bs[0][ca0 + 0][ra0] = bP0.x; Bs[0][ca0 + 1][ra0] = bP0.y;
    Bs[0][ca0 + 2][ra0] = bP0.z; Bs[0][ca0 + 3][ra0] = bP0.w;
    Bs[0][ca0 + 0][ra1] = bP1.x; Bs[0][ca0 + 1][ra1] = bP1.y;
    Bs[0][ca0 + 2][ra1] = bP1.z; Bs[0][ca0 + 3][ra1] = bP1.w;
    __syncthreads();

    #pragma unroll
    for (int k0 = 0; k0 < K; k0 += 16) {
        constexpr int NIT = K / 16;
        const int it = k0 / 16;
        const int p  = it & 1;
        const bool hasNext = (it + 1) < NIT;

        // prefetch next tile (LDG latency hidden behind the compute below)
        if (hasNext) {
            const int kn = k0 + 16;
            aP0 = *(const float4*)(Arow0 + kn);
            aP1 = *(const float4*)(Arow1 + kn);
            bP0 = *(const float4*)(Brow0 + kn);
            bP1 = *(const float4*)(Brow1 + kn);
        }

        #pragma unroll
        for (int k = 0; k < 16; ++k) {
            *(float4*)&ar[0] = *(const float4*)&As[p][k][ty * 8];
            *(float4*)&ar[4] = *(const float4*)&As[p][k][ty * 8 + 4];
            ulonglong2 b01 = *(const ulonglong2*)&Bs[p][k][tx * 8];
            ulonglong2 b23 = *(const ulonglong2*)&Bs[p][k][tx * 8 + 4];
            brp[0] = b01.x; brp[1] = b01.y; brp[2] = b23.x; brp[3] = b23.y;
            #pragma unroll
            for (int i = 0; i < 8; ++i) {
                unsigned int au = __float_as_uint(ar[i]);
                unsigned long long arp;
                asm("mov.b64 %0, {%1, %1};" : "=l"(arp) : "r"(au));
                #pragma unroll
                for (int jp = 0; jp < 4; ++jp)
                    asm("fma.rn.f32x2 %0, %1, %2, %0;"
                        : "+l"(acc2[i][jp]) : "l"(arp), "l"(brp[jp]));
            }
        }

        if (hasNext) {
            const int q = p ^ 1;     // safe: buf q last read before previous barrier
            As[q][ca0 + 0][ra0] = aP0.x; As[q][ca0 + 1][ra0] = aP0.y;
            As[q][ca0 + 2][ra0] = aP0.z; As[q][ca0 + 3][ra0] = aP0.w;
            As[q][ca0 + 0][ra1] = aP1.x; As[q][ca0 + 1][ra1] = aP1.y;
            As[q][ca0 + 2][ra1] = aP1.z; As[q][ca0 + 3][ra1] = aP1.w;
            Bs[q][ca0 + 0][ra0] = bP0.x; Bs[q][ca0 + 1][ra0] = bP0.y;
            Bs[q][ca0 + 2][ra0] = bP0.z; Bs[q][ca0 + 3][ra0] = bP0.w;
            Bs[q][ca0 + 0][ra1] = bP1.x; Bs[q][ca0 + 1][ra1] = bP1.y;
            Bs[q][ca0 + 2][ra1] = bP1.z; Bs[q][ca0 + 3][ra1] = bP1.w;
            __syncthreads();
        }
    }

    // bias (per output column)
    float bv[8];
    #pragma unroll
    for (int j = 0; j < 8; ++j) {
        int c = colBase + tx * 8 + j;
        float b = bias1 ? bias1[c] : 0.f;
        if (bias2) b += bias2[c];
        bv[j] = b;
    }

    #pragma unroll
    for (int i = 0; i < 8; ++i) {
        int r = rowBase + ty * 8 + i;
        int c = colBase + tx * 8;
        float2 p0 = up2(acc2[i][0]), p1 = up2(acc2[i][1]);
        float2 p2 = up2(acc2[i][2]), p3 = up2(acc2[i][3]);
        float4 o0, o1;
        o0.x = p0.x + bv[0]; o0.y = p0.y + bv[1];
        o0.z = p1.x + bv[2]; o0.w = p1.y + bv[3];
        o1.x = p2.x + bv[4]; o1.y = p2.y + bv[5];
        o1.z = p3.x + bv[6]; o1.w = p3.y + bv[7];
        *(float4*)(C + (size_t)r * Nn + c)     = o0;
        *(float4*)(C + (size_t)r * Nn + c + 4) = o1;
    }

    // fused GATv2 score epilogue: writes g_esrc = exp(s_src) for rows < NN
    // (reference's flat indexing pulls scores from the (b=0,v=0) block only).
    if (SCORES) {
        if (rowBase < NN) {
            const int head = tx >> 2;              // cols tx*8..tx*8+7 lie in one head
            // att layout: [HEADS][2*OUT_F]; src weights are [0,32) per head
            float aw_s[8];
            #pragma unroll
            for (int j = 0; j < 8; ++j) {
                int coff = ((tx & 3) << 3) + j;    // 0..31 within head
                aw_s[j] = att[head * 64 + coff];
            }
            #pragma unroll
            for (int i = 0; i < 8; ++i) {
                int r = rowBase + ty * 8 + i;
                float ps = 0.f;
                #pragma unroll
                for (int j = 0; j < 8; ++j) {
                    float2 pr = up2(acc2[i][j >> 1]);
                    float hv = (j & 1) ? pr.y : pr.x;  // bias1==nullptr here
                    float lr = hv > 0.f ? hv : NEG_SLOPE * hv;
                    ps = fmaf(aw_s[j], lr, ps);
                }
                // reduce over the 4 adjacent lanes (tx & 3) sharing head+row
                #pragma unroll
                for (int o = 1; o <= 2; o <<= 1)
                    ps += __shfl_xor_sync(0xffffffffu, ps, o);
                if ((tx & 3) == 0 && r < NN)
                    g_esrc[r * HEADS + head] = __expf(ps);
            }
        }
    }
}

// ---------------- CSR build --------------------------------------------------
// Edge dtype detection is done per-block: if edge_index is int64 (values in
// [0,4000)), every odd 32-bit word of the first 512 entries is the zero high
// half; if int32, those words are real ids ~U[0,4000) and P(all zero) == 0.
__device__ __forceinline__ int block_edge_is32(const unsigned int* __restrict__ w) {
    unsigned int any = 0;
    for (int i = threadIdx.x; i < 512; i += blockDim.x)
        any |= w[2 * i + 1];
    return __syncthreads_or(any != 0u);   // nonzero -> int32
}

__global__ void count_edges(const unsigned int* __restrict__ w) {
    const int is32 = block_edge_is32(w);
    int e = blockIdx.x * blockDim.x + threadIdx.x;
    if (e < EE) {
        int dst = is32 ? ((const int*)w)[EE + e]
                       : (int)((const long long*)w)[EE + e];
        atomicAdd(&g_deg[dst], 1);
    }
}

// Warp-shuffle scan (2 barriers). Adds the +1 self-loop itself and resets
// g_deg to zero for the next replay (graph determinism: zero at load,
// count -> scan -> reset). Also initializes g_esrc = 1.0 (= exp(0)) for node
// ids >= NN, whose score rows are zero in the reference's flat indexing.
// (Runs before gemm1's score epilogue, which writes only ids < NN.)
__global__ __launch_bounds__(1024) void scan_deg() {
    __shared__ int wsum[32];
    const int tid = threadIdx.x;
    const int lane = tid & 31, wid = tid >> 5;
    const int base = tid * 4;
    int l[4], s = 0;
    #pragma unroll
    for (int j = 0; j < 4; ++j) {
        int idx = base + j;
        l[j] = (idx < NTOT) ? (g_deg[idx] + 1) : 0;
        s += l[j];
    }
    #pragma unroll
    for (int j = 0; j < 4; ++j)
        if (base + j < NTOT) g_deg[base + j] = 0;

    // init exp(s_src)=1 for out-of-block-0 node ids
    for (int i = NN * HEADS + tid; i < NTOT * HEADS; i += 1024)
        g_esrc[i] = 1.0f;

    int sc = s;   // inclusive scan over per-thread sums
    #pragma unroll
    for (int o = 1; o < 32; o <<= 1) {
        int v = __shfl_up_sync(0xffffffffu, sc, o);
        if (lane >= o) sc += v;
    }
    if (lane == 31) wsum[wid] = sc;
    __syncthreads();
    if (wid == 0) {
        int ws = wsum[lane];
        #pragma unroll
        for (int o = 1; o < 32; o <<= 1) {
            int v = __shfl_up_sync(0xffffffffu, ws, o);
            if (lane >= o) ws += v;
        }
        wsum[lane] = ws;
    }
    __syncthreads();
    int exc = sc - s + (wid ? wsum[wid - 1] : 0);
    #pragma unroll
    for (int j = 0; j < 4; ++j) {
        int idx = base + j;
        if (idx < NTOT) { g_off[idx] = exc; g_cur[idx] = exc; }
        exc += l[j];
    }
    if (tid == 1023) g_off[NTOT] = wsum[31];
}

__global__ void fill_csr(const unsigned int* __restrict__ w) {
    const int is32 = block_edge_is32(w);
    int e = blockIdx.x * blockDim.x + threadIdx.x;
    if (e >= ETOT) return;
    int src, dst;
    if (e < EE) {
        if (is32) { src = ((const int*)w)[e]; dst = ((const int*)w)[EE + e]; }
        else      { src = (int)((const long long*)w)[e];
                    dst = (int)((const long long*)w)[EE + e]; }
    } else {
        src = dst = e - EE;
    }
    int pos = atomicAdd(&g_cur[dst], 1);
    g_csr[pos] = src;
}

// ---------------- GAT softmax + aggregate (one block per dst) ----------------
// alpha_e = exp(s_src[src_e]) / sum_e' exp(s_src[src_e']): the per-dst s_dst
// term and the max subtraction cancel exactly in the softmax. 2 passes.
__global__ __launch_bounds__(128) void gat_aggregate()
{
    int d = blockIdx.x;              // 0..3999
    int tid = threadIdx.x;           // thread owns feature f=tid
    int hh = tid >> 5, lane = tid & 31;
    int b = d / NN, dloc = d - b * NN;
    int beg = g_off[d], end = g_off[d + 1];

    __shared__ float denom[HEADS];

    // pass 1: per-head denominator (warp hh handles head hh, lanes over edges)
    float lsum = 0.f;
    for (int j = beg + lane; j < end; j += 32)
        lsum += g_esrc[g_csr[j] * HEADS + hh];
    #pragma unroll
    for (int o = 16; o; o >>= 1)
        lsum += __shfl_xor_sync(0xffffffffu, lsum, o);
    if (lane == 0) denom[hh] = lsum;
    __syncthreads();

    const float inv = 1.f / denom[hh];
    float acc0 = 0.f, acc1 = 0.f, acc2 = 0.f, acc3 = 0.f;
    const int blo = b * NN, bhi = blo + NN;
    const size_t vstride = (size_t)NN * DD;   // view stride in floats
    for (int j = beg; j < end; ++j) {
        int src = g_csr[j];
        if (src >= blo && src < bhi) {     // only same-block srcs have nonzero rows
            float alpha = g_esrc[src * HEADS + hh] * inv;
            const float* hp = g_h + ((size_t)(b * VV) * NN + (src - blo)) * DD + tid;
            acc0 = fmaf(alpha, hp[0],           acc0);
            acc1 = fmaf(alpha, hp[vstride],     acc1);
            acc2 = fmaf(alpha, hp[2 * vstride], acc2);
            acc3 = fmaf(alpha, hp[3 * vstride], acc3);
        }
    }
    size_t ob = ((size_t)(b * VV) * NN + dloc) * DD + tid;
    g_hgat[ob]               = acc0;
    g_hgat[ob + vstride]     = acc1;
    g_hgat[ob + 2 * vstride] = acc2;
    g_hgat[ob + 3 * vstride] = acc3;
}

// ---------------- per-node 4-view MHA (warp = head) --------------------------
__global__ __launch_bounds__(128) void mha_attn()
{
    int nid = blockIdx.x;            // 0..3999 (= b*N+n)
    int b = nid / NN, n = nid - b * NN;
    int tid = threadIdx.x;
    int hh = tid >> 5, lane = tid & 31;

    float q[4], k[4], v[4];
    #pragma unroll
    for (int vv = 0; vv < 4; ++vv) {
        size_t r = ((size_t)(b * VV + vv) * NN + n) * 384;
        q[vv] = g_qkv[r +       hh * 32 + lane];
        k[vv] = g_qkv[r + 128 + hh * 32 + lane];
        v[vv] = g_qkv[r + 256 + hh * 32 + lane];
    }

    const float inv_sqrt = 0.1767766952966369f; // 1/sqrt(32)
    float s[4][4];
    #pragma unroll
    for (int qv = 0; qv < 4; ++qv)
        #pragma unroll
        for (int kv = 0; kv < 4; ++kv) {
            float p = q[qv] * k[kv];
            #pragma unroll
            for (int o = 16; o; o >>= 1)
                p += __shfl_xor_sync(0xffffffffu, p, o);
            s[qv][kv] = p * inv_sqrt;
        }

    #pragma unroll
    for (int qv = 0; qv < 4; ++qv) {
        float mx = fmaxf(fmaxf(s[qv][0], s[qv][1]), fmaxf(s[qv][2], s[qv][3]));
        float e0 = __expf(s[qv][0] - mx), e1 = __expf(s[qv][1] - mx);
        float e2 = __expf(s[qv][2] - mx), e3 = __expf(s[qv][3] - mx);
        float inv = 1.f / (e0 + e1 + e2 + e3);
        float o = (e0 * v[0] + e1 * v[1] + e2 * v[2] + e3 * v[3]) * inv;
        g_ao[((size_t)(b * VV + qv) * NN + n) * DD + hh * 32 + lane] = o;
    }
}

// ---------------- launch -----------------------------------------------------
// Launch order puts gemm1 at index 3: the harness's ncu capture lands on
// launch index 3 (observed R7/R10), so this round profiles the GEMM.
extern "C" void kernel_launch(void* const* d_in, const int* in_sizes, int n_in,
                              void* d_out, int out_size)
{
    const float* x          = (const float*)d_in[0];
    const float* W          = (const float*)d_in[1];
    const float* att        = (const float*)d_in[2];
    const float* in_proj_w  = (const float*)d_in[3];
    const float* in_proj_b  = (const float*)d_in[4];
    const float* out_proj_w = (const float*)d_in[5];
    const float* out_proj_b = (const float*)d_in[6];
    const float* bias       = (const float*)d_in[7];
    const unsigned int* edge_index = (const unsigned int*)d_in[8]; // int32 or int64
    float* out = (float*)d_out;

    float* h    = nullptr; cudaGetSymbolAddress((void**)&h,    g_h);
    float* hgat = nullptr; cudaGetSymbolAddress((void**)&hgat, g_hgat);
    float* qkv  = nullptr; cudaGetSymbolAddress((void**)&qkv,  g_qkv);
    float* ao   = nullptr; cudaGetSymbolAddress((void**)&ao,   g_ao);

    // 0-2) CSR by dst (independent of gemm1; deg zero at start, scan resets it)
    count_edges<<<(EE + 255) / 256, 256>>>(edge_index);
    scan_deg<<<1, 1024>>>();
    fill_csr<<<(ETOT + 255) / 256, 256>>>(edge_index);

    // 3) h = x @ W^T  [16000,64]x[128,64]^T -> [16000,128], fused exp(s_src)
    gemm_tn<IN_F, true><<<dim3(1, 125), 256>>>(x, W, nullptr, nullptr, att, h, DD);

    // 4) segment softmax + aggregate (2-pass, exp-free)
    gat_aggregate<<<NTOT, 128>>>();

    // 5) in_proj: qkv = h_gat @ in_proj_w^T + b  [16000,128]x[384,128]^T
    gemm_tn<DD, false><<<dim3(3, 125), 256>>>(hgat, in_proj_w, in_proj_b, nullptr, nullptr, qkv, 384);

    // 6) per-node MHA over 4 views
    mha_attn<<<NTOT, 128>>>();

    // 7) out_proj + out_proj_b + bias, written straight to d_out
    gemm_tn<DD, false><<<dim3(1, 125), 256>>>(ao, out_proj_w, out_proj_b, bias, nullptr, out, DD);
}

// round 15
// speedup vs baseline: 1.4631x; 1.0670x over previous
#include <cuda_runtime.h>
#include <cuda_bf16.h>
#include <cstdint>
#include <cstring>

// Problem constants
#define BB 4
#define VV 4
#define NN 1000
#define IN_F 64
#define HEADS 4
#define OUT_F 32
#define DD 128           // HEADS*OUT_F
#define EE 64000
#define NTOT 4000        // B*N
#define ETOT 68000       // E + self loops
#define ROWS 16000       // B*V*N
#define NEG_SLOPE 0.2f

// ---------------- scratch (static device globals; no allocation) -------------
__device__ float g_h[ROWS * DD];        // GAT linear output, row=(b*4+v)*1000+n
__device__ float g_hgat[ROWS * DD];     // GAT aggregated output
__device__ float g_qkv[ROWS * 384];     // in_proj output
__device__ float g_ao[ROWS * DD];       // attention output
__device__ float g_esrc[NTOT * HEADS];  // exp(s_src); [NN..) set to 1.0 by scan_deg
__device__ int   g_deg[NTOT];           // zero at load; scan resets to zero each run
__device__ int   g_off[NTOT + 1];
__device__ int   g_cur[NTOT];
__device__ int   g_csr[ETOT];

// unpack packed f32x2
__device__ __forceinline__ float2 up2(unsigned long long v) {
    float2 f; memcpy(&f, &v, 8); return f;
}

// ---------------- tiled fp32 GEMM: C[M][Nn] = A[M][K] @ B[Nn][K]^T -----------
// 128x128 tile, 512 threads (16 warps -> 4/SMSP for latency hiding; R12 ncu
// showed 256-thread version at occ=13%, issue=27%, fma=24% = latency-bound),
// 8x4 microtile, K-step 16, K a template constant. FFMA2 inner product.
// A-operand smem read is a warp-broadcast (row group == warp id).
// Double-buffered smem: one barrier per mainloop iteration.
// SCORES: fused GATv2 score epilogue writing g_esrc = exp(s_src) for rows < NN.
// Requires: M % 128 == 0, Nn % 128 == 0, K % 16 == 0 (true for all call sites).
template <int K, bool SCORES>
__global__ __launch_bounds__(512) void gemm_tn(
    const float* __restrict__ A, const float* __restrict__ Bm,
    const float* __restrict__ bias1, const float* __restrict__ bias2,
    const float* __restrict__ att,
    float* __restrict__ C, int Nn)
{
    __shared__ float As[2][16][132];   // [buf][k][m], padded (132 % 32 == 4)
    __shared__ float Bs[2][16][132];   // [buf][k][n]
    const int tid = threadIdx.x;
    const int tx = tid & 31;        // 0..31 -> col group (4 cols)
    const int ty = tid >> 5;        // 0..15 -> row group (8 rows) == warp id
    const int rowBase = blockIdx.y * 128;
    const int colBase = blockIdx.x * 128;

    // per-thread load coordinates: one A row-quad, one B row-quad
    const int ra = tid >> 2;             // 0..127
    const int ca = (tid & 3) << 2;       // 0,4,8,12

    unsigned long long acc2[8][2] = {};  // [i][jp] -> cols (2jp, 2jp+1), fp32x2
    float ar[8];
    unsigned long long brp[2];
    float4 aP, bP;

    const float* Arow = A  + (size_t)(rowBase + ra) * K + ca;
    const float* Brow = Bm + (size_t)(colBase + ra) * K + ca;

    // prologue: prefetch tile k0=0 and commit to buffer 0
    aP = *(const float4*)(Arow);
    bP = *(const float4*)(Brow);
    As[0][ca + 0][ra] = aP.x; As[0][ca + 1][ra] = aP.y;
    As[0][ca + 2][ra] = aP.z; As[0][ca + 3][ra] = aP.w;
    Bs[0][ca + 0][ra] = bP.x; Bs[0][ca + 1][ra] = bP.y;
    Bs[0][ca + 2][ra] = bP.z; Bs[0][ca + 3][ra] = bP.w;
    __syncthreads();

    #pragma unroll
    for (int k0 = 0; k0 < K; k0 += 16) {
        constexpr int NIT = K / 16;
        const int it = k0 / 16;
        const int p  = it & 1;
        const bool hasNext = (it + 1) < NIT;

        // prefetch next tile (LDG latency hidden behind the compute below)
        if (hasNext) {
            aP = *(const float4*)(Arow + k0 + 16);
            bP = *(const float4*)(Brow + k0 + 16);
        }

        #pragma unroll
        for (int k = 0; k < 16; ++k) {
            // A read: ty uniform per warp -> broadcast, conflict-free
            *(float4*)&ar[0] = *(const float4*)&As[p][k][ty * 8];
            *(float4*)&ar[4] = *(const float4*)&As[p][k][ty * 8 + 4];
            // B read: lane-stride 16B -> conflict-free
            ulonglong2 b01 = *(const ulonglong2*)&Bs[p][k][tx * 4];
            brp[0] = b01.x; brp[1] = b01.y;
            #pragma unroll
            for (int i = 0; i < 8; ++i) {
                unsigned int au = __float_as_uint(ar[i]);
                unsigned long long arp;
                asm("mov.b64 %0, {%1, %1};" : "=l"(arp) : "r"(au));
                #pragma unroll
                for (int jp = 0; jp < 2; ++jp)
                    asm("fma.rn.f32x2 %0, %1, %2, %0;"
                        : "+l"(acc2[i][jp]) : "l"(arp), "l"(brp[jp]));
            }
        }

        if (hasNext) {
            const int q = p ^ 1;     // safe: buf q last read before previous barrier
            As[q][ca + 0][ra] = aP.x; As[q][ca + 1][ra] = aP.y;
            As[q][ca + 2][ra] = aP.z; As[q][ca + 3][ra] = aP.w;
            Bs[q][ca + 0][ra] = bP.x; Bs[q][ca + 1][ra] = bP.y;
            Bs[q][ca + 2][ra] = bP.z; Bs[q][ca + 3][ra] = bP.w;
            __syncthreads();
        }
    }

    // bias (per output column)
    float bv[4];
    #pragma unroll
    for (int j = 0; j < 4; ++j) {
        int c = colBase + tx * 4 + j;
        float b = bias1 ? bias1[c] : 0.f;
        if (bias2) b += bias2[c];
        bv[j] = b;
    }

    #pragma unroll
    for (int i = 0; i < 8; ++i) {
        int r = rowBase + ty * 8 + i;
        int c = colBase + tx * 4;
        float2 p0 = up2(acc2[i][0]), p1 = up2(acc2[i][1]);
        float4 o;
        o.x = p0.x + bv[0]; o.y = p0.y + bv[1];
        o.z = p1.x + bv[2]; o.w = p1.y + bv[3];
        *(float4*)(C + (size_t)r * Nn + c) = o;
    }

    // fused GATv2 score epilogue: writes g_esrc = exp(s_src) for rows < NN
    // (reference's flat indexing pulls scores from the (b=0,v=0) block only).
    if (SCORES) {
        if (rowBase < NN) {
            const int head = tx >> 3;              // cols tx*4..tx*4+3 lie in one head
            // att layout: [HEADS][2*OUT_F]; src weights are [0,32) per head
            float aw_s[4];
            #pragma unroll
            for (int j = 0; j < 4; ++j) {
                int coff = ((tx & 7) << 2) + j;    // 0..31 within head
                aw_s[j] = att[head * 64 + coff];
            }
            #pragma unroll
            for (int i = 0; i < 8; ++i) {
                int r = rowBase + ty * 8 + i;
                float ps = 0.f;
                #pragma unroll
                for (int j = 0; j < 4; ++j) {
                    float2 pr = up2(acc2[i][j >> 1]);
                    float hv = (j & 1) ? pr.y : pr.x;  // bias1==nullptr here
                    float lr = hv > 0.f ? hv : NEG_SLOPE * hv;
                    ps = fmaf(aw_s[j], lr, ps);
                }
                // reduce over the 8 adjacent lanes (tx & 7) sharing head+row
                #pragma unroll
                for (int o = 1; o <= 4; o <<= 1)
                    ps += __shfl_xor_sync(0xffffffffu, ps, o);
                if ((tx & 7) == 0 && r < NN)
                    g_esrc[r * HEADS + head] = __expf(ps);
            }
        }
    }
}

// ---------------- CSR build --------------------------------------------------
// Edge dtype detection is done per-block: if edge_index is int64 (values in
// [0,4000)), every odd 32-bit word of the first 512 entries is the zero high
// half; if int32, those words are real ids ~U[0,4000) and P(all zero) == 0.
__device__ __forceinline__ int block_edge_is32(const unsigned int* __restrict__ w) {
    unsigned int any = 0;
    for (int i = threadIdx.x; i < 512; i += blockDim.x)
        any |= w[2 * i + 1];
    return __syncthreads_or(any != 0u);   // nonzero -> int32
}

__global__ void count_edges(const unsigned int* __restrict__ w) {
    const int is32 = block_edge_is32(w);
    int e = blockIdx.x * blockDim.x + threadIdx.x;
    if (e < EE) {
        int dst = is32 ? ((const int*)w)[EE + e]
                       : (int)((const long long*)w)[EE + e];
        atomicAdd(&g_deg[dst], 1);
    }
}

// Warp-shuffle scan (2 barriers). Adds the +1 self-loop itself and resets
// g_deg to zero for the next replay (graph determinism: zero at load,
// count -> scan -> reset). Also initializes g_esrc = 1.0 (= exp(0)) for node
// ids >= NN, whose score rows are zero in the reference's flat indexing.
__global__ __launch_bounds__(1024) void scan_deg() {
    __shared__ int wsum[32];
    const int tid = threadIdx.x;
    const int lane = tid & 31, wid = tid >> 5;
    const int base = tid * 4;
    int l[4], s = 0;
    #pragma unroll
    for (int j = 0; j < 4; ++j) {
        int idx = base + j;
        l[j] = (idx < NTOT) ? (g_deg[idx] + 1) : 0;
        s += l[j];
    }
    #pragma unroll
    for (int j = 0; j < 4; ++j)
        if (base + j < NTOT) g_deg[base + j] = 0;

    // init exp(s_src)=1 for out-of-block-0 node ids
    for (int i = NN * HEADS + tid; i < NTOT * HEADS; i += 1024)
        g_esrc[i] = 1.0f;

    int sc = s;   // inclusive scan over per-thread sums
    #pragma unroll
    for (int o = 1; o < 32; o <<= 1) {
        int v = __shfl_up_sync(0xffffffffu, sc, o);
        if (lane >= o) sc += v;
    }
    if (lane == 31) wsum[wid] = sc;
    __syncthreads();
    if (wid == 0) {
        int ws = wsum[lane];
        #pragma unroll
        for (int o = 1; o < 32; o <<= 1) {
            int v = __shfl_up_sync(0xffffffffu, ws, o);
            if (lane >= o) ws += v;
        }
        wsum[lane] = ws;
    }
    __syncthreads();
    int exc = sc - s + (wid ? wsum[wid - 1] : 0);
    #pragma unroll
    for (int j = 0; j < 4; ++j) {
        int idx = base + j;
        if (idx < NTOT) { g_off[idx] = exc; g_cur[idx] = exc; }
        exc += l[j];
    }
    if (tid == 1023) g_off[NTOT] = wsum[31];
}

__global__ void fill_csr(const unsigned int* __restrict__ w) {
    const int is32 = block_edge_is32(w);
    int e = blockIdx.x * blockDim.x + threadIdx.x;
    if (e >= ETOT) return;
    int src, dst;
    if (e < EE) {
        if (is32) { src = ((const int*)w)[e]; dst = ((const int*)w)[EE + e]; }
        else      { src = (int)((const long long*)w)[e];
                    dst = (int)((const long long*)w)[EE + e]; }
    } else {
        src = dst = e - EE;
    }
    int pos = atomicAdd(&g_cur[dst], 1);
    g_csr[pos] = src;
}

// ---------------- GAT softmax + aggregate (one block per dst) ----------------
// alpha_e = exp(s_src[src_e]) / sum_e' exp(s_src[src_e']): the per-dst s_dst
// term and the max subtraction cancel exactly in the softmax. 2 passes.
__global__ __launch_bounds__(128) void gat_aggregate()
{
    int d = blockIdx.x;              // 0..3999
    int tid = threadIdx.x;           // thread owns feature f=tid
    int hh = tid >> 5, lane = tid & 31;
    int b = d / NN, dloc = d - b * NN;
    int beg = g_off[d], end = g_off[d + 1];

    __shared__ float denom[HEADS];

    // pass 1: per-head denominator (warp hh handles head hh, lanes over edges)
    float lsum = 0.f;
    for (int j = beg + lane; j < end; j += 32)
        lsum += g_esrc[g_csr[j] * HEADS + hh];
    #pragma unroll
    for (int o = 16; o; o >>= 1)
        lsum += __shfl_xor_sync(0xffffffffu, lsum, o);
    if (lane == 0) denom[hh] = lsum;
    __syncthreads();

    const float inv = 1.f / denom[hh];
    float acc0 = 0.f, acc1 = 0.f, acc2 = 0.f, acc3 = 0.f;
    const int blo = b * NN, bhi = blo + NN;
    const size_t vstride = (size_t)NN * DD;   // view stride in floats
    for (int j = beg; j < end; ++j) {
        int src = g_csr[j];
        if (src >= blo && src < bhi) {     // only same-block srcs have nonzero rows
            float alpha = g_esrc[src * HEADS + hh] * inv;
            const float* hp = g_h + ((size_t)(b * VV) * NN + (src - blo)) * DD + tid;
            acc0 = fmaf(alpha, hp[0],           acc0);
            acc1 = fmaf(alpha, hp[vstride],     acc1);
            acc2 = fmaf(alpha, hp[2 * vstride], acc2);
            acc3 = fmaf(alpha, hp[3 * vstride], acc3);
        }
    }
    size_t ob = ((size_t)(b * VV) * NN + dloc) * DD + tid;
    g_hgat[ob]               = acc0;
    g_hgat[ob + vstride]     = acc1;
    g_hgat[ob + 2 * vstride] = acc2;
    g_hgat[ob + 3 * vstride] = acc3;
}

// ---------------- per-node 4-view MHA (warp = head) --------------------------
__global__ __launch_bounds__(128) void mha_attn()
{
    int nid = blockIdx.x;            // 0..3999 (= b*N+n)
    int b = nid / NN, n = nid - b * NN;
    int tid = threadIdx.x;
    int hh = tid >> 5, lane = tid & 31;

    float q[4], k[4], v[4];
    #pragma unroll
    for (int vv = 0; vv < 4; ++vv) {
        size_t r = ((size_t)(b * VV + vv) * NN + n) * 384;
        q[vv] = g_qkv[r +       hh * 32 + lane];
        k[vv] = g_qkv[r + 128 + hh * 32 + lane];
        v[vv] = g_qkv[r + 256 + hh * 32 + lane];
    }

    const float inv_sqrt = 0.1767766952966369f; // 1/sqrt(32)
    float s[4][4];
    #pragma unroll
    for (int qv = 0; qv < 4; ++qv)
        #pragma unroll
        for (int kv = 0; kv < 4; ++kv) {
            float p = q[qv] * k[kv];
            #pragma unroll
            for (int o = 16; o; o >>= 1)
                p += __shfl_xor_sync(0xffffffffu, p, o);
            s[qv][kv] = p * inv_sqrt;
        }

    #pragma unroll
    for (int qv = 0; qv < 4; ++qv) {
        float mx = fmaxf(fmaxf(s[qv][0], s[qv][1]), fmaxf(s[qv][2], s[qv][3]));
        float e0 = __expf(s[qv][0] - mx), e1 = __expf(s[qv][1] - mx);
        float e2 = __expf(s[qv][2] - mx), e3 = __expf(s[qv][3] - mx);
        float inv = 1.f / (e0 + e1 + e2 + e3);
        float o = (e0 * v[0] + e1 * v[1] + e2 * v[2] + e3 * v[3]) * inv;
        g_ao[((size_t)(b * VV + qv) * NN + n) * DD + hh * 32 + lane] = o;
    }
}

// ---------------- launch -----------------------------------------------------
// gemm1 stays at launch index 3 (the harness's ncu capture slot): this round
// re-measures the SAME gemm shape with 512 threads for a clean A/B vs R12.
extern "C" void kernel_launch(void* const* d_in, const int* in_sizes, int n_in,
                              void* d_out, int out_size)
{
    const float* x          = (const float*)d_in[0];
    const float* W          = (const float*)d_in[1];
    const float* att        = (const float*)d_in[2];
    const float* in_proj_w  = (const float*)d_in[3];
    const float* in_proj_b  = (const float*)d_in[4];
    const float* out_proj_w = (const float*)d_in[5];
    const float* out_proj_b = (const float*)d_in[6];
    const float* bias       = (const float*)d_in[7];
    const unsigned int* edge_index = (const unsigned int*)d_in[8]; // int32 or int64
    float* out = (float*)d_out;

    float* h    = nullptr; cudaGetSymbolAddress((void**)&h,    g_h);
    float* hgat = nullptr; cudaGetSymbolAddress((void**)&hgat, g_hgat);
    float* qkv  = nullptr; cudaGetSymbolAddress((void**)&qkv,  g_qkv);
    float* ao   = nullptr; cudaGetSymbolAddress((void**)&ao,   g_ao);

    // 0-2) CSR by dst (independent of gemm1; deg zero at start, scan resets it)
    count_edges<<<(EE + 255) / 256, 256>>>(edge_index);
    scan_deg<<<1, 1024>>>();
    fill_csr<<<(ETOT + 255) / 256, 256>>>(edge_index);

    // 3) h = x @ W^T  [16000,64]x[128,64]^T -> [16000,128], fused exp(s_src)
    gemm_tn<IN_F, true><<<dim3(1, 125), 512>>>(x, W, nullptr, nullptr, att, h, DD);

    // 4) segment softmax + aggregate (2-pass, exp-free)
    gat_aggregate<<<NTOT, 128>>>();

    // 5) in_proj: qkv = h_gat @ in_proj_w^T + b  [16000,128]x[384,128]^T
    gemm_tn<DD, false><<<dim3(3, 125), 512>>>(hgat, in_proj_w, in_proj_b, nullptr, nullptr, qkv, 384);

    // 6) per-node MHA over 4 views
    mha_attn<<<NTOT, 128>>>();

    // 7) out_proj + out_proj_b + bias, written straight to d_out
    gemm_tn<DD, false><<<dim3(1, 125), 512>>>(ao, out_proj_w, out_proj_b, bias, nullptr, out, DD);
}